// round 1
// baseline (speedup 1.0000x reference)
#include <cuda_runtime.h>
#include <math.h>

// Problem constants: B=4, N=16, K=16, H=64, O=1
#define ZB 4
#define NN 16
#define NK 16
#define NH 64

// Scratch (allocation-free rule: __device__ globals)
// P[z][i][j][k][c] : basis tensor, 4*16*16*16*3 floats = 192 KB
__device__ float g_P[ZB * NN * NN * NK * 3];
// h[z][a][h] accumulator: 4*16*64 = 4096 floats
__device__ float g_h[ZB * NN * NH];

// ---------------------------------------------------------------------------
// Kernel 1: compute basis P and zero the h accumulator.
// P[z,i,j,k,c] = cutoff(norm) * exp(-beta*(exp(-norm)-mean_k)^2) * diff_c / norm_sq
// ---------------------------------------------------------------------------
__global__ void k1_basis(const float* __restrict__ x) {
    int tid = blockIdx.x * blockDim.x + threadIdx.x;

    if (tid < ZB * NN * NH) g_h[tid] = 0.0f;

    if (tid >= ZB * NN * NN * NK) return;

    int k = tid & 15;
    int j = (tid >> 4) & 15;
    int i = (tid >> 8) & 15;
    int z = tid >> 12;

    const float* xi = x + (z * NN + i) * 3;
    const float* xj = x + (z * NN + j) * 3;
    float d0 = xi[0] - xj[0];
    float d1 = xi[1] - xj[1];
    float d2 = xi[2] - xj[2];

    float ns = d0 * d0 + d1 * d1 + d2 * d2 + 1e-5f;  // norm_sq + EPSILON
    float norm = sqrtf(ns);

    const float start = expf(-5.0f);                       // exp(-CUT_HI+CUT_LO)
    float mean = start + (float)k * (1.0f - start) * (1.0f / 15.0f);
    float bden = 0.125f * (1.0f - start);                  // 2/K*(1-start)
    float beta = 1.0f / (bden * bden);

    float cutoff = (norm < 5.0f)
                 ? 0.5f * (cospif(norm * 0.2f) + 1.0f)     // cos(pi*norm/5)
                 : 0.0f;
    float e = expf(-norm);                                 // alpha = 1, CUT_LO = 0
    float dd = e - mean;
    float smear = cutoff * expf(-beta * dd * dd);

    float s_over = smear / ns;                             // smear * (diff / norm_sq)

    int base = tid * 3;                                    // [z][i][j][k] layout matches tid
    g_P[base + 0] = s_over * d0;
    g_P[base + 1] = s_over * d1;
    g_P[base + 2] = s_over * d2;
}

// ---------------------------------------------------------------------------
// Kernel 2: stream W once. One block per (a,b,d) -> contiguous 64 KB slice of W
// over (e,k,h). Build coef[j=e*16+k][z] = dot_c(P[z,a,b,k,:], P[z,d,e,k,:])
// in shared, then accumulate h[z,a,h] += coef * W.
// ---------------------------------------------------------------------------
__global__ void __launch_bounds__(256) k2_main(const float* __restrict__ W) {
    __shared__ float4 scoef[256];          // [j] -> (z0,z1,z2,z3)
    __shared__ float  sred[16 * 256];      // [g][z*64+h]

    int blk = blockIdx.x;                  // a*256 + b*16 + d
    int d = blk & 15;
    int b = (blk >> 4) & 15;
    int a = blk >> 8;

    int t = threadIdx.x;

    // --- coefficient table: thread t computes j = t ---
    {
        int e = t >> 4;
        int k = t & 15;
        float cf[4];
#pragma unroll
        for (int z = 0; z < 4; z++) {
            const float* p1 = &g_P[((((z * NN + a) * NN + b) * NK) + k) * 3];
            const float* p2 = &g_P[((((z * NN + d) * NN + e) * NK) + k) * 3];
            cf[z] = p1[0] * p2[0] + p1[1] * p2[1] + p1[2] * p2[2];
        }
        scoef[t] = make_float4(cf[0], cf[1], cf[2], cf[3]);
    }
    __syncthreads();

    // --- main streaming loop ---
    int h4 = t & 15;                       // which float4 of the 64 h values
    int g  = t >> 4;                       // group 0..15 over j-rows
    const float4* Wb = (const float4*)(W + (size_t)blk * (NN * NK * NH));

    float acc0x = 0.f, acc0y = 0.f, acc0z = 0.f, acc0w = 0.f;
    float acc1x = 0.f, acc1y = 0.f, acc1z = 0.f, acc1w = 0.f;
    float acc2x = 0.f, acc2y = 0.f, acc2z = 0.f, acc2w = 0.f;
    float acc3x = 0.f, acc3y = 0.f, acc3z = 0.f, acc3w = 0.f;

#pragma unroll
    for (int it = 0; it < 16; it++) {
        int j = g + (it << 4);             // row index (e*16+k); warp reads 512B contiguous
        float4 w = __ldcs(&Wb[j * 16 + h4]);
        float4 cf = scoef[j];
        acc0x += cf.x * w.x; acc0y += cf.x * w.y; acc0z += cf.x * w.z; acc0w += cf.x * w.w;
        acc1x += cf.y * w.x; acc1y += cf.y * w.y; acc1z += cf.y * w.z; acc1w += cf.y * w.w;
        acc2x += cf.z * w.x; acc2y += cf.z * w.y; acc2z += cf.z * w.z; acc2w += cf.z * w.w;
        acc3x += cf.w * w.x; acc3y += cf.w * w.y; acc3z += cf.w * w.z; acc3w += cf.w * w.w;
    }

    // --- block reduction over the 16 groups ---
    {
        float4* r = (float4*)sred;
        int base = g * 64 + h4;            // float4 index into [g][z][h4]
        r[base + 0 * 16 * 0 + 0] = make_float4(acc0x, acc0y, acc0z, acc0w); // placeholder, fixed below
    }
    // (rewrite cleanly without the placeholder hack)
    {
        float4* r4 = (float4*)sred;        // sred as float4[16][4][16]: [g][z][h4]
        int base = (g * 4) * 16 + h4;
        r4[base + 0 * 16] = make_float4(acc0x, acc0y, acc0z, acc0w);
        r4[base + 1 * 16] = make_float4(acc1x, acc1y, acc1z, acc1w);
        r4[base + 2 * 16] = make_float4(acc2x, acc2y, acc2z, acc2w);
        r4[base + 3 * 16] = make_float4(acc3x, acc3y, acc3z, acc3w);
    }
    __syncthreads();

    // thread t owns (z = t>>6, h = t&63); sum across 16 groups, one atomic.
    float s = 0.0f;
#pragma unroll
    for (int g2 = 0; g2 < 16; g2++) s += sred[g2 * 256 + t];

    int z = t >> 6;
    int h = t & 63;
    atomicAdd(&g_h[(z * NN + a) * NH + h], s);
}

// ---------------------------------------------------------------------------
// Kernel 3: out[z,a] = silu(h[z,a,:]) . w_fc + b_fc
// ---------------------------------------------------------------------------
__global__ void k3_head(const float* __restrict__ w_fc,
                        const float* __restrict__ b_fc,
                        float* __restrict__ out) {
    int t = threadIdx.x;                   // 0..63 = z*16+a
    if (t >= ZB * NN) return;
    const float* hp = &g_h[t * NH];
    float acc = 0.0f;
#pragma unroll
    for (int h = 0; h < NH; h++) {
        float v = hp[h];
        float s = v / (1.0f + expf(-v));
        acc += s * w_fc[h];
    }
    out[t] = acc + b_fc[0];
}

// ---------------------------------------------------------------------------
extern "C" void kernel_launch(void* const* d_in, const int* in_sizes, int n_in,
                              void* d_out, int out_size) {
    const float* x   = nullptr;
    const float* W   = nullptr;
    const float* wfc = nullptr;
    const float* bfc = nullptr;
    for (int i = 0; i < n_in; i++) {
        long long s = in_sizes[i];
        if      (s == (long long)ZB * NN * 3)                 x   = (const float*)d_in[i];
        else if (s == (long long)NN * NN * NN * NN * NK * NH) W   = (const float*)d_in[i];
        else if (s == NH)                                     wfc = (const float*)d_in[i];
        else if (s == 1)                                      bfc = (const float*)d_in[i];
    }

    k1_basis<<<64, 256>>>(x);
    k2_main<<<NN * NN * NN, 256>>>(W);   // 4096 blocks
    k3_head<<<1, 64>>>(wfc, bfc, (float*)d_out);
}